// round 1
// baseline (speedup 1.0000x reference)
#include <cuda_runtime.h>

// Causal (strict, PixelSNAIL) attention, B=4, S=4096, Cqk=Cv=256, fp32.
// FA2-style online softmax. Packed fp32 (fma.rn.f32x2) on both GEMMs.

typedef unsigned long long u64;

__device__ __forceinline__ u64 ffma2(u64 a, u64 b, u64 c) {
    u64 d;
    asm("fma.rn.f32x2 %0, %1, %2, %3;" : "=l"(d) : "l"(a), "l"(b), "l"(c));
    return d;
}
__device__ __forceinline__ u64 fmul2(u64 a, u64 b) {
    u64 d;
    asm("mul.rn.f32x2 %0, %1, %2;" : "=l"(d) : "l"(a), "l"(b));
    return d;
}
__device__ __forceinline__ u64 pack2(float x, float y) {
    u64 d;
    asm("mov.b64 %0, {%1, %2};" : "=l"(d) : "f"(x), "f"(y));
    return d;
}
__device__ __forceinline__ float2 unpack2(u64 a) {
    float2 f;
    asm("mov.b64 {%0, %1}, %2;" : "=f"(f.x), "=f"(f.y) : "l"(a));
    return f;
}

constexpr int S_LEN   = 4096;   // 64*64 spatial positions
constexpr int C_DIM   = 256;
constexpr int BQ      = 64;     // query rows per CTA
constexpr int BK      = 64;     // key rows per block
constexpr int NTHREADS = 256;
constexpr int PS_STRIDE = 68;   // padded P row stride (floats)

constexpr int Q_OFF = 0;
constexpr int K_OFF = 64 * 256;
constexpr int V_OFF = 2 * 64 * 256;
constexpr int P_OFF = 3 * 64 * 256;
constexpr int SMEM_FLOATS = 3 * 64 * 256 + 64 * PS_STRIDE;   // 53504
constexpr int SMEM_BYTES  = SMEM_FLOATS * 4;                 // 214016

// Load a 64x256 fp32 tile (global row-major, contiguous) into smem with an
// XOR swizzle on the float4 column index: phys_c4 = c4 ^ ((row>>2)&7).
// Global reads coalesced (consecutive tid -> consecutive c4, same row).
// Smem stores conflict-free (32 consecutive c4 XOR const = permutation).
__device__ __forceinline__ void load_tile_sw(float* dst, const float* src, float scale) {
    const float4* s4 = reinterpret_cast<const float4*>(src);
    float4* d4 = reinterpret_cast<float4*>(dst);
    int tid = threadIdx.x;
    #pragma unroll
    for (int it = 0; it < 16; ++it) {
        int idx = tid + it * NTHREADS;       // 0..4095 float4s
        int r   = idx >> 6;                  // row 0..63
        int c4  = idx & 63;                  // float4 col 0..63
        float4 v = s4[idx];                  // == s4[r*64 + c4]
        v.x *= scale; v.y *= scale; v.z *= scale; v.w *= scale;
        d4[(r << 6) + (c4 ^ ((r >> 2) & 7))] = v;
    }
}

__global__ void __launch_bounds__(NTHREADS, 1)
causal_attn_kernel(const float* __restrict__ Q, const float* __restrict__ K,
                   const float* __restrict__ V, float* __restrict__ Out)
{
    extern __shared__ float smem[];
    float* Qs = smem + Q_OFF;
    float* Ks = smem + K_OFF;
    float* Vs = smem + V_OFF;
    float* Ps = smem + P_OFF;

    const int tid = threadIdx.x;
    const int tx  = tid & 15;          // key-col / out-col group
    const int ty  = tid >> 4;          // query-row group (0..15)
    const int batch = blockIdx.x & 3;
    const int qt    = 63 - (blockIdx.x >> 2);   // heavy diagonal tiles first
    const int q0    = qt * BQ;

    // scale folded into Q at load: 1/sqrt(256)
    load_tile_sw(Qs, Q + (size_t)(batch * S_LEN + q0) * C_DIM, 0.0625f);

    float m[4], l[4];
    u64 o[4][8];                       // packed O accum: rows 4ty+i, col float4 groups {tx+16k}
    #pragma unroll
    for (int i = 0; i < 4; ++i) {
        m[i] = -1e30f; l[i] = 0.0f;
        #pragma unroll
        for (int k = 0; k < 8; ++k) o[i][k] = 0ull;
    }

    const ulonglong2* Qs2 = reinterpret_cast<const ulonglong2*>(Qs);
    const ulonglong2* Ks2 = reinterpret_cast<const ulonglong2*>(Ks);
    const ulonglong2* Vs2 = reinterpret_cast<const ulonglong2*>(Vs);
    const int sq = ty & 7;
    const int sk = tx & 7;

    for (int kb = 0; kb <= qt; ++kb) {
        load_tile_sw(Ks, K + (size_t)(batch * S_LEN + kb * BK) * C_DIM, 1.0f);
        load_tile_sw(Vs, V + (size_t)(batch * S_LEN + kb * BK) * C_DIM, 1.0f);
        __syncthreads();

        // ---- S = Q K^T (4x4 per thread), packed over c-parity ----
        u64 s2[4][4];
        #pragma unroll
        for (int i = 0; i < 4; ++i)
            #pragma unroll
            for (int j = 0; j < 4; ++j) s2[i][j] = 0ull;

        #pragma unroll 2
        for (int c4 = 0; c4 < 64; ++c4) {
            ulonglong2 qv[4], kv[4];
            const int qc = c4 ^ sq;
            const int kc = c4 ^ sk;
            #pragma unroll
            for (int i = 0; i < 4; ++i) qv[i] = Qs2[((4 * ty + i) << 6) + qc];
            #pragma unroll
            for (int j = 0; j < 4; ++j) kv[j] = Ks2[((4 * tx + j) << 6) + kc];
            #pragma unroll
            for (int i = 0; i < 4; ++i)
                #pragma unroll
                for (int j = 0; j < 4; ++j) {
                    s2[i][j] = ffma2(qv[i].x, kv[j].x, s2[i][j]);
                    s2[i][j] = ffma2(qv[i].y, kv[j].y, s2[i][j]);
                }
        }

        float s[4][4];
        #pragma unroll
        for (int i = 0; i < 4; ++i)
            #pragma unroll
            for (int j = 0; j < 4; ++j) {
                float2 f = unpack2(s2[i][j]);
                s[i][j] = f.x + f.y;
            }

        if (kb == qt) {
            // strict causal: mask key >= query (local indices, same block origin)
            #pragma unroll
            for (int i = 0; i < 4; ++i)
                #pragma unroll
                for (int j = 0; j < 4; ++j)
                    if (4 * tx + j >= 4 * ty + i) s[i][j] = -1e30f;
        }

        // ---- online softmax over this block ----
        float mb[4];
        #pragma unroll
        for (int i = 0; i < 4; ++i) {
            mb[i] = fmaxf(fmaxf(s[i][0], s[i][1]), fmaxf(s[i][2], s[i][3]));
            #pragma unroll
            for (int off = 8; off >= 1; off >>= 1)
                mb[i] = fmaxf(mb[i], __shfl_xor_sync(0xffffffffu, mb[i], off));
        }

        float p[4][4], rs[4];
        #pragma unroll
        for (int i = 0; i < 4; ++i) {
            const float mn  = fmaxf(m[i], mb[i]);
            const float cor = __expf(m[i] - mn);   // exp(0)=1 or underflow->0; never NaN
            m[i] = mn;
            rs[i] = 0.0f;
            #pragma unroll
            for (int j = 0; j < 4; ++j) {
                p[i][j] = __expf(s[i][j] - mn);    // masked -> exp(-1e30) == 0
                rs[i] += p[i][j];
            }
            const u64 c2 = pack2(cor, cor);
            #pragma unroll
            for (int k = 0; k < 8; ++k) o[i][k] = fmul2(o[i][k], c2);
            l[i] *= cor;
        }
        #pragma unroll
        for (int i = 0; i < 4; ++i) {
            #pragma unroll
            for (int off = 8; off >= 1; off >>= 1)
                rs[i] += __shfl_xor_sync(0xffffffffu, rs[i], off);
            l[i] += rs[i];
        }

        // publish P tile
        #pragma unroll
        for (int i = 0; i < 4; ++i)
            reinterpret_cast<float4*>(Ps + (4 * ty + i) * PS_STRIDE)[tx] =
                make_float4(p[i][0], p[i][1], p[i][2], p[i][3]);
        __syncthreads();

        // ---- O += P V (4 rows x 16 cols per thread), packed over col pairs ----
        #pragma unroll 2
        for (int j = 0; j < 64; ++j) {
            const int sv = (j >> 2) & 7;
            u64 pj[4];
            #pragma unroll
            for (int i = 0; i < 4; ++i) {
                const float pv = Ps[(4 * ty + i) * PS_STRIDE + j];  // broadcast
                pj[i] = pack2(pv, pv);
            }
            ulonglong2 vv[4];
            #pragma unroll
            for (int kk = 0; kk < 4; ++kk)
                vv[kk] = Vs2[(j << 6) + ((tx + 16 * kk) ^ sv)];
            #pragma unroll
            for (int i = 0; i < 4; ++i)
                #pragma unroll
                for (int kk = 0; kk < 4; ++kk) {
                    o[i][2 * kk]     = ffma2(pj[i], vv[kk].x, o[i][2 * kk]);
                    o[i][2 * kk + 1] = ffma2(pj[i], vv[kk].y, o[i][2 * kk + 1]);
                }
        }
        __syncthreads();   // guard K/V/P overwrite next iter
    }

    // ---- epilogue: Out = O / l ; global row 0 is exactly 0 (reference semantics) ----
    float4* O4 = reinterpret_cast<float4*>(Out);
    #pragma unroll
    for (int i = 0; i < 4; ++i) {
        const int row = q0 + 4 * ty + i;
        const float inv = (row == 0) ? 0.0f : 1.0f / l[i];
        const size_t base = ((size_t)(batch * S_LEN) + row) * (C_DIM / 4);
        #pragma unroll
        for (int kk = 0; kk < 4; ++kk) {
            float2 a  = unpack2(o[i][2 * kk]);
            float2 b2 = unpack2(o[i][2 * kk + 1]);
            O4[base + tx + 16 * kk] = make_float4(a.x * inv, a.y * inv, b2.x * inv, b2.y * inv);
        }
    }
}

extern "C" void kernel_launch(void* const* d_in, const int* in_sizes, int n_in,
                              void* d_out, int out_size) {
    const float* Q = (const float*)d_in[0];
    const float* K = (const float*)d_in[1];
    const float* V = (const float*)d_in[2];
    float* O = (float*)d_out;

    // Not a stream op: executes immediately, safe under graph capture. Idempotent.
    cudaFuncSetAttribute(causal_attn_kernel,
                         cudaFuncAttributeMaxDynamicSharedMemorySize, SMEM_BYTES);

    // 4 batches x 64 query tiles; heavy tiles mapped to low blockIdx.
    causal_attn_kernel<<<256, NTHREADS, SMEM_BYTES>>>(Q, K, V, O);
}